// round 13
// baseline (speedup 1.0000x reference)
#include <cuda_runtime.h>
#include <cuda_bf16.h>
#include <cstdint>
#include <cstddef>

#define B_    2
#define N_    2048
#define DIM_  1024
#define H_    16
#define DH_   64
#define MEM_  1024
#define CTX_  3072
#define SCALE_ 0.125f

// ---------------- scratch (static device globals; no allocation) ----------------
__device__ float    g_Q  [B_ * N_ * DIM_];         // 16 MB
__device__ float    g_KV [B_ * CTX_ * 2 * DIM_];   // 48 MB
__device__ float    g_pos[N_ * DH_];               // 512 KB
__device__ float    g_posp[8 * N_ * DH_];          // 4 MB  split-K partials
__device__ float    g_PDT[134217728];              // 512 MB PDT[b,h][j2][i] (shifted)
__device__ float    g_O  [B_ * N_ * DIM_];         // 16 MB
__device__ unsigned g_Kh [B_ * CTX_ * 512];        // K hi (bf16x2, feature pairs)
__device__ unsigned g_Kl [B_ * CTX_ * 512];        // K lo
__device__ unsigned g_Vth[B_ * H_ * DH_ * (CTX_/2)]; // V^T hi (key pairs)
__device__ unsigned g_Vtl[B_ * H_ * DH_ * (CTX_/2)]; // V^T lo

// =====================================================================
// bf16x3 helpers
// =====================================================================
__device__ __forceinline__ void bsplit2(float x, float y, unsigned& h, unsigned& l)
{
    asm("cvt.rn.bf16x2.f32 %0, %1, %2;" : "=r"(h) : "f"(y), "f"(x));
    float xr = x - __uint_as_float(h << 16);
    float yr = y - __uint_as_float(h & 0xFFFF0000u);
    asm("cvt.rn.bf16x2.f32 %0, %1, %2;" : "=r"(l) : "f"(yr), "f"(xr));
}

__device__ __forceinline__ void mma_bf16(float* c, const unsigned* a, const unsigned* b)
{
    asm volatile(
        "mma.sync.aligned.m16n8k16.row.col.f32.bf16.bf16.f32 "
        "{%0,%1,%2,%3}, {%4,%5,%6,%7}, {%8,%9}, {%0,%1,%2,%3};\n"
        : "+f"(c[0]), "+f"(c[1]), "+f"(c[2]), "+f"(c[3])
        : "r"(a[0]), "r"(a[1]), "r"(a[2]), "r"(a[3]), "r"(b[0]), "r"(b[1]));
}

__device__ __forceinline__ void cp_async16(void* s, const void* g)
{
    unsigned a = (unsigned)__cvta_generic_to_shared(s);
    asm volatile("cp.async.cg.shared.global [%0], [%1], 16;" :: "r"(a), "l"(g));
}

// =====================================================================
// Split-bf16 tensor-core GEMM:  C = A @ B + bias  (bf16x3, m16n8k16)
// =====================================================================
__global__ __launch_bounds__(256) void gemm_bf16(
    const float* __restrict__ Alo, int MLo, size_t sAlo,
    const float* __restrict__ Ahi, size_t sAhi,
    const float* __restrict__ Bm, const float* __restrict__ bias,
    float* __restrict__ C, size_t sC,
    int N, int K,
    unsigned* __restrict__ Kh, unsigned* __restrict__ Kl, int kcols)
{
    __shared__ __align__(16) unsigned AsH[128][12];
    __shared__ __align__(16) unsigned AsL[128][12];
    __shared__ __align__(16) unsigned BsH[8][136];
    __shared__ __align__(16) unsigned BsL[8][136];

    const int batch   = blockIdx.z;
    const int rowBase = blockIdx.y * 128;
    const int colBase = blockIdx.x * 128;
    const int tid  = threadIdx.x;
    const int wid  = tid >> 5, lane = tid & 31;
    const int wm   = wid & 3,  wn   = wid >> 2;
    const int g    = lane >> 2, qq  = lane & 3;

    const int ar = tid >> 2;
    const int ac = (tid & 3) * 4;
    const float* aptr[2];
#pragma unroll
    for (int i = 0; i < 2; ++i) {
        int r = rowBase + ar + 64 * i;
        aptr[i] = ((r < MLo) ? (Alo + (size_t)batch * sAlo + (size_t)r * K)
                             : (Ahi + (size_t)batch * sAhi + (size_t)(r - MLo) * K)) + ac;
    }
    const int kp = tid >> 5;
    const int n0 = (tid & 31) * 4;
    const float* bptr0 = Bm + (size_t)(2 * kp) * N + colBase + n0;
    const float* bptr1 = bptr0 + N;

    float4 ga[2], gb0, gb1;
#pragma unroll
    for (int i = 0; i < 2; ++i) ga[i] = *(const float4*)(aptr[i]);
    gb0 = *(const float4*)(bptr0);
    gb1 = *(const float4*)(bptr1);

    float acc[2][8][4];
#pragma unroll
    for (int a = 0; a < 2; ++a)
#pragma unroll
        for (int b = 0; b < 8; ++b)
#pragma unroll
            for (int c = 0; c < 4; ++c) acc[a][b][c] = 0.f;

    for (int k0 = 0; k0 < K; k0 += 16) {
#pragma unroll
        for (int i = 0; i < 2; ++i) {
            unsigned h0, l0, h1, l1;
            bsplit2(ga[i].x, ga[i].y, h0, l0);
            bsplit2(ga[i].z, ga[i].w, h1, l1);
            int r = ar + 64 * i, cpr = ac >> 1;
            AsH[r][cpr] = h0; AsH[r][cpr + 1] = h1;
            AsL[r][cpr] = l0; AsL[r][cpr + 1] = l1;
        }
        {
            uint4 bh, bl;
            bsplit2(gb0.x, gb1.x, bh.x, bl.x);
            bsplit2(gb0.y, gb1.y, bh.y, bl.y);
            bsplit2(gb0.z, gb1.z, bh.z, bl.z);
            bsplit2(gb0.w, gb1.w, bh.w, bl.w);
            *(uint4*)&BsH[kp][n0] = bh;
            *(uint4*)&BsL[kp][n0] = bl;
        }
        __syncthreads();

        if (k0 + 16 < K) {
#pragma unroll
            for (int i = 0; i < 2; ++i) ga[i] = *(const float4*)(aptr[i] + k0 + 16);
            gb0 = *(const float4*)(bptr0 + (size_t)(k0 + 16) * N);
            gb1 = *(const float4*)(bptr1 + (size_t)(k0 + 16) * N);
        }

        unsigned bH[8][2], bL[8][2];
#pragma unroll
        for (int tn = 0; tn < 8; ++tn) {
            int col = wn * 64 + tn * 8 + g;
            bH[tn][0] = BsH[qq][col]; bH[tn][1] = BsH[qq + 4][col];
            bL[tn][0] = BsL[qq][col]; bL[tn][1] = BsL[qq + 4][col];
        }
#pragma unroll
        for (int tm = 0; tm < 2; ++tm) {
            int r0 = wm * 32 + tm * 16 + g;
            unsigned aHf[4], aLf[4];
            aHf[0] = AsH[r0][qq];     aHf[1] = AsH[r0 + 8][qq];
            aHf[2] = AsH[r0][qq + 4]; aHf[3] = AsH[r0 + 8][qq + 4];
            aLf[0] = AsL[r0][qq];     aLf[1] = AsL[r0 + 8][qq];
            aLf[2] = AsL[r0][qq + 4]; aLf[3] = AsL[r0 + 8][qq + 4];
#pragma unroll
            for (int tn = 0; tn < 8; ++tn) mma_bf16(acc[tm][tn], aHf, bH[tn]);
#pragma unroll
            for (int tn = 0; tn < 8; ++tn) mma_bf16(acc[tm][tn], aHf, bL[tn]);
#pragma unroll
            for (int tn = 0; tn < 8; ++tn) mma_bf16(acc[tm][tn], aLf, bH[tn]);
        }
        __syncthreads();
    }

    float* Cb = C + (size_t)batch * sC;
#pragma unroll
    for (int tm = 0; tm < 2; ++tm) {
#pragma unroll
        for (int tn = 0; tn < 8; ++tn) {
            int row = rowBase + wm * 32 + tm * 16 + g;
            int col = colBase + wn * 64 + tn * 8 + 2 * qq;
            float b0 = bias[col], b1 = bias[col + 1];
            float2 v0 = make_float2(acc[tm][tn][0] + b0, acc[tm][tn][1] + b1);
            float2 v1 = make_float2(acc[tm][tn][2] + b0, acc[tm][tn][3] + b1);
            *(float2*)(Cb + (size_t)row * N + col) = v0;
            *(float2*)(Cb + (size_t)(row + 8) * N + col) = v1;
            if (Kh != nullptr && col < kcols) {
                unsigned hh, ll;
                size_t kr = ((size_t)batch * CTX_ + row) * (kcols >> 1) + (col >> 1);
                bsplit2(v0.x, v0.y, hh, ll);
                Kh[kr] = hh; Kl[kr] = ll;
                bsplit2(v1.x, v1.y, hh, ll);
                size_t kr2 = kr + (size_t)8 * (kcols >> 1);
                Kh[kr2] = hh; Kl[kr2] = ll;
            }
        }
    }
}

// =====================================================================
// pos' split-K
// =====================================================================
__global__ __launch_bounds__(256) void pos_part(
    const float* __restrict__ A, const float* __restrict__ Bm, float* __restrict__ Cp)
{
    __shared__ float As[16][65];
    __shared__ float Bs[16][64];

    const int kOff    = blockIdx.x * 128;
    const int rowBase = blockIdx.y * 64;
    const int tid = threadIdx.x;
    const int tx = tid & 15, ty = tid >> 4;

    const int arow = tid >> 2;
    const int ac   = (tid & 3) * 4;
    const int brow = tid >> 4;
    const int bc   = (tid & 15) * 4;

    const float* Aptr = A + (size_t)(rowBase + arow) * DIM_ + kOff;
    float acc[4][4] = {};

    for (int k0 = 0; k0 < 128; k0 += 16) {
        float4 av = *(const float4*)(Aptr + k0 + ac);
        float4 bv = *(const float4*)(Bm + (size_t)(kOff + k0 + brow) * DH_ + bc);
        __syncthreads();
        As[ac + 0][arow] = av.x; As[ac + 1][arow] = av.y;
        As[ac + 2][arow] = av.z; As[ac + 3][arow] = av.w;
        *(float4*)&Bs[brow][bc] = bv;
        __syncthreads();
#pragma unroll
        for (int kk = 0; kk < 16; ++kk) {
            float a0 = As[kk][ty * 4 + 0], a1 = As[kk][ty * 4 + 1];
            float a2 = As[kk][ty * 4 + 2], a3 = As[kk][ty * 4 + 3];
            float4 b4 = *(const float4*)&Bs[kk][tx * 4];
            acc[0][0] += a0 * b4.x; acc[0][1] += a0 * b4.y; acc[0][2] += a0 * b4.z; acc[0][3] += a0 * b4.w;
            acc[1][0] += a1 * b4.x; acc[1][1] += a1 * b4.y; acc[1][2] += a1 * b4.z; acc[1][3] += a1 * b4.w;
            acc[2][0] += a2 * b4.x; acc[2][1] += a2 * b4.y; acc[2][2] += a2 * b4.z; acc[2][3] += a2 * b4.w;
            acc[3][0] += a3 * b4.x; acc[3][1] += a3 * b4.y; acc[3][2] += a3 * b4.z; acc[3][3] += a3 * b4.w;
        }
    }

    float* Cb = Cp + (size_t)blockIdx.x * (N_ * DH_);
#pragma unroll
    for (int a = 0; a < 4; ++a) {
        int row = rowBase + ty * 4 + a;
        *(float4*)(Cb + (size_t)row * DH_ + tx * 4) =
            make_float4(acc[a][0], acc[a][1], acc[a][2], acc[a][3]);
    }
}

__global__ __launch_bounds__(256) void pos_reduce(
    const float* __restrict__ Cp, const float* __restrict__ bias, float* __restrict__ C)
{
    int i4 = blockIdx.x * 256 + threadIdx.x;
    float4 s = ((const float4*)Cp)[i4];
#pragma unroll
    for (int k = 1; k < 8; ++k) {
        float4 t = ((const float4*)(Cp + (size_t)k * (N_ * DH_)))[i4];
        s.x += t.x; s.y += t.y; s.z += t.z; s.w += t.w;
    }
    int col = (i4 & 15) * 4;
    float4 bv = *(const float4*)(bias + col);
    s.x += bv.x; s.y += bv.y; s.z += bv.z; s.w += bv.w;
    ((float4*)C)[i4] = s;
}

// =====================================================================
// vt_kernel: V^T split
// =====================================================================
__global__ __launch_bounds__(256) void vt_kernel(
    const float* __restrict__ KV, unsigned* __restrict__ Vth, unsigned* __restrict__ Vtl)
{
    const int bh = blockIdx.y;
    const int b = bh >> 4, h = bh & 15;
    const int J0 = blockIdx.x * 64;
    __shared__ float Vs[64][65];
    const int tid = threadIdx.x;

#pragma unroll
    for (int u = 0; u < 4; ++u) {
        int idx = u * 256 + tid;
        int row = idx >> 4, c4 = (idx & 15) * 4;
        float4 v = *(const float4*)(KV + ((size_t)b * CTX_ + J0 + row) * (2 * DIM_) + DIM_ + h * DH_ + c4);
        Vs[row][c4] = v.x; Vs[row][c4 + 1] = v.y; Vs[row][c4 + 2] = v.z; Vs[row][c4 + 3] = v.w;
    }
    __syncthreads();

#pragma unroll
    for (int u = 0; u < 8; ++u) {
        int idx = u * 256 + tid;
        int d = idx >> 5, jp = idx & 31;
        unsigned hh, ll;
        bsplit2(Vs[2 * jp][d], Vs[2 * jp + 1][d], hh, ll);
        size_t o = ((size_t)bh * DH_ + d) * (CTX_ / 2) + (J0 >> 1) + jp;
        Vth[o] = hh; Vtl[o] = ll;
    }
}

// =====================================================================
// rd_kernel: pos dots on tensor cores, output in SHIFTED layout
// PDT[b,h][j2][i] = SCALE * q_i . pos'[j2 - i + 2047]
// =====================================================================
__global__ __launch_bounds__(256) void rd_kernel(
    const float* __restrict__ Q, const float* __restrict__ Pos, float* __restrict__ PDT)
{
    const int I0 = blockIdx.y * 128;
    const int P0 = blockIdx.x * 128;
    if (I0 + P0 + 254 < 2047) return;          // all j2 < 0: never read

    const int bh = blockIdx.z;
    const int b  = bh >> 4, h = bh & 15;

    __shared__ __align__(16) unsigned shraw[9216];   // union: PsH/PsL then Ts
    unsigned (*PsH)[36] = (unsigned(*)[36])shraw;
    unsigned (*PsL)[36] = (unsigned(*)[36])(shraw + 128 * 36);
    float    (*Ts)[66]  = (float(*)[66])shraw;

    const int tid  = threadIdx.x;
    const int wid  = tid >> 5, lane = tid & 31;
    const int wm   = wid & 3,  wn   = wid >> 2;
    const int g    = lane >> 2, qq  = lane & 3;

#pragma unroll
    for (int u = 0; u < 8; ++u) {
        int idx = tid + u * 256;
        int prow = idx >> 4, c4 = (idx & 15) * 4;
        float4 v = *(const float4*)(Pos + (size_t)(P0 + prow) * DH_ + c4);
        unsigned h0, l0, h1, l1;
        bsplit2(v.x, v.y, h0, l0);
        bsplit2(v.z, v.w, h1, l1);
        int pc = (idx & 15) * 2;
        PsH[prow][pc] = h0; PsH[prow][pc + 1] = h1;
        PsL[prow][pc] = l0; PsL[prow][pc + 1] = l1;
    }

    unsigned aH[2][4][4], aL[2][4][4];
#pragma unroll
    for (int tm = 0; tm < 2; ++tm) {
        const float* q0 = Q + ((size_t)(b * N_) + I0 + wm * 32 + tm * 16 + g) * DIM_ + h * DH_;
        const float* q8 = q0 + 8 * DIM_;
#pragma unroll
        for (int ks = 0; ks < 4; ++ks) {
            float2 xa = *(const float2*)(q0 + ks * 16 + 2 * qq);
            float2 xb = *(const float2*)(q0 + ks * 16 + 2 * qq + 8);
            float2 ya = *(const float2*)(q8 + ks * 16 + 2 * qq);
            float2 yb = *(const float2*)(q8 + ks * 16 + 2 * qq + 8);
            bsplit2(xa.x, xa.y, aH[tm][ks][0], aL[tm][ks][0]);
            bsplit2(ya.x, ya.y, aH[tm][ks][1], aL[tm][ks][1]);
            bsplit2(xb.x, xb.y, aH[tm][ks][2], aL[tm][ks][2]);
            bsplit2(yb.x, yb.y, aH[tm][ks][3], aL[tm][ks][3]);
        }
    }
    __syncthreads();

    float acc[2][8][4];
#pragma unroll
    for (int a = 0; a < 2; ++a)
#pragma unroll
        for (int t = 0; t < 8; ++t)
#pragma unroll
            for (int c = 0; c < 4; ++c) acc[a][t][c] = 0.f;

#pragma unroll
    for (int ks = 0; ks < 4; ++ks) {
#pragma unroll
        for (int tn = 0; tn < 8; ++tn) {
            int col = wn * 64 + tn * 8 + g;
            unsigned bh2[2], bl2[2];
            bh2[0] = PsH[col][8 * ks + qq];     bh2[1] = PsH[col][8 * ks + qq + 4];
            bl2[0] = PsL[col][8 * ks + qq];     bl2[1] = PsL[col][8 * ks + qq + 4];
            mma_bf16(acc[0][tn], aH[0][ks], bh2);
            mma_bf16(acc[1][tn], aH[1][ks], bh2);
            mma_bf16(acc[0][tn], aH[0][ks], bl2);
            mma_bf16(acc[1][tn], aH[1][ks], bl2);
            mma_bf16(acc[0][tn], aL[0][ks], bh2);
            mma_bf16(acc[1][tn], aL[1][ks], bh2);
        }
    }

    // ---- transpose to shifted layout; two p-halves of 64 ----
    float* base = PDT + ((size_t)bh << 22);
#pragma unroll
    for (int ph = 0; ph < 2; ++ph) {
        __syncthreads();
        if (wn == ph) {
#pragma unroll
            for (int tm = 0; tm < 2; ++tm)
#pragma unroll
                for (int tn = 0; tn < 8; ++tn) {
                    int r = wm * 32 + tm * 16 + g;
                    int c = tn * 8 + 2 * qq;
                    Ts[r][c]         = acc[tm][tn][0] * SCALE_;
                    Ts[r][c + 1]     = acc[tm][tn][1] * SCALE_;
                    Ts[r + 8][c]     = acc[tm][tn][2] * SCALE_;
                    Ts[r + 8][c + 1] = acc[tm][tn][3] * SCALE_;
                }
        }
        __syncthreads();
        const int jbase = I0 + P0 + ph * 64 - 2047;
        for (int d = wid; d <= 190; d += 8) {
            int j2 = jbase + d;
            if (j2 < 0) continue;
            int iLo = d - 63; if (iLo < 0) iLo = 0;
            int iHi = d < 127 ? d : 127;
            float* dst = base + (size_t)j2 * N_ + I0;
            for (int ib = iLo + lane; ib <= iHi; ib += 32)
                dst[ib] = Ts[ib][d - ib];
        }
    }
}

// =====================================================================
// Tensor-core flash attention (bf16x3; pre-split K/V; staged Pdm;
// 128 q-rows/block, 256 threads, 2 CTAs/SM)
// =====================================================================
#define SM_K 1152                 // 32 rows x 36 words, per stage per (h/l)
#define SM_V 2304                 // 64 rows x 36 words
#define SM_P 4224                 // 32 rows x 132 words
#define OFF_KL 2304
#define OFF_VH 4608
#define OFF_VL 9216
#define OFF_PD 13824
#define OFF_EM 22272
#define SMEM_ATTN ((OFF_EM + 1024) * 4)    // 93184 B

__global__ __launch_bounds__(256, 2) void attn_kernel(
    const float* __restrict__ Q,
    const unsigned* __restrict__ Khg, const unsigned* __restrict__ Klg,
    const unsigned* __restrict__ Vthg, const unsigned* __restrict__ Vtlg,
    const float* __restrict__ PDT, const float* __restrict__ expire,
    float* __restrict__ O)
{
    extern __shared__ unsigned smu[];
    float* em_s = (float*)(smu + OFF_EM);

    const int b = blockIdx.z, h = blockIdx.y;
    const int tid = threadIdx.x;
    const int I0 = blockIdx.x * 128;
    const int W = tid >> 5, lane = tid & 31;
    const int g = lane >> 2, qq = lane & 3;
    const int bh64 = (b * H_ + h) * DH_;

    *(float4*)&em_s[tid * 4] = *(const float4*)(expire + b * MEM_ + tid * 4);

    unsigned aH[4][4], aL[4][4];
    {
        const float* q0 = Q + ((size_t)(b * N_) + I0 + W * 16 + g) * DIM_ + h * DH_;
        const float* q8 = q0 + 8 * DIM_;
#pragma unroll
        for (int ks = 0; ks < 4; ++ks) {
            float2 xa = *(const float2*)(q0 + ks * 16 + 2 * qq);
            float2 xb = *(const float2*)(q0 + ks * 16 + 2 * qq + 8);
            float2 ya = *(const float2*)(q8 + ks * 16 + 2 * qq);
            float2 yb = *(const float2*)(q8 + ks * 16 + 2 * qq + 8);
            bsplit2(xa.x * SCALE_, xa.y * SCALE_, aH[ks][0], aL[ks][0]);
            bsplit2(ya.x * SCALE_, ya.y * SCALE_, aH[ks][1], aL[ks][1]);
            bsplit2(xb.x * SCALE_, xb.y * SCALE_, aH[ks][2], aL[ks][2]);
            bsplit2(yb.x * SCALE_, yb.y * SCALE_, aH[ks][3], aL[ks][3]);
        }
    }

    float o[8][4];
#pragma unroll
    for (int t = 0; t < 8; ++t)
#pragma unroll
        for (int c = 0; c < 4; ++c) o[t][c] = 0.f;
    float m0 = -1e30f, m1 = -1e30f, l0 = 0.f, l1 = 0.f;

    const float* pdtb = PDT + (((size_t)(b * H_ + h)) << 22);
    const int ntiles = (MEM_ + I0 + 128) / 32;

    auto load_stage = [&](int sb, int jt) {
        unsigned* KhD = smu + sb * SM_K;
        unsigned* KlD = smu + OFF_KL + sb * SM_K;
        unsigned* VhD = smu + OFF_VH + sb * SM_V;
        unsigned* VlD = smu + OFF_VL + sb * SM_V;
        {
            int row = tid >> 3, part = tid & 7;
            size_t srk = ((size_t)b * CTX_ + jt + row) * 512 + h * 32 + part * 4;
            cp_async16(KhD + row * 36 + part * 4, Khg + srk);
            cp_async16(KlD + row * 36 + part * 4, Klg + srk);
        }
        {
            int row = tid >> 2, part = tid & 3;
            size_t srv = ((size_t)bh64 + row) * (CTX_ / 2) + (jt >> 1) + part * 4;
            cp_async16(VhD + row * 36 + part * 4, Vthg + srv);
            cp_async16(VlD + row * 36 + part * 4, Vtlg + srv);
        }
        if (jt >= MEM_) {
            float* PdD = (float*)(smu + OFF_PD + sb * SM_P);
            const float* src = pdtb + (size_t)(jt - MEM_) * N_ + I0;
#pragma unroll
            for (int u = 0; u < 4; ++u) {
                int e = u * 256 + tid;
                int row = e >> 5, part = e & 31;
                cp_async16(PdD + row * 132 + part * 4, src + (size_t)row * N_ + part * 4);
            }
        }
    };

    load_stage(0, 0);
    asm volatile("cp.async.commit_group;");

    for (int t = 0; t < ntiles; ++t) {
        const int st = t & 1;
        const int j0 = t * 32;
        if (t + 1 < ntiles)
            load_stage(st ^ 1, j0 + 32);
        asm volatile("cp.async.commit_group;");
        asm volatile("cp.async.wait_group 1;");
        __syncthreads();

        const unsigned* KhC = smu + st * SM_K;
        const unsigned* KlC = smu + OFF_KL + st * SM_K;
        const unsigned* VhC = smu + OFF_VH + st * SM_V;
        const unsigned* VlC = smu + OFF_VL + st * SM_V;
        const float*    PdC = (const float*)(smu + OFF_PD + st * SM_P);

        // ---- S = Q K^T (pass-major) ----
        float s[4][4];
#pragma unroll
        for (int tt = 0; tt < 4; ++tt)
#pragma unroll
            for (int c = 0; c < 4; ++c) s[tt][c] = 0.f;

#pragma unroll
        for (int ks = 0; ks < 4; ++ks) {
            unsigned bhf[4][2], blf[4][2];
#pragma unroll
            for (int tt = 0; tt < 4; ++tt) {
                int base = (tt * 8 + g) * 36 + ks * 8 + qq;
                bhf[tt][0] = KhC[base]; bhf[tt][1] = KhC[base + 4];
                blf[tt][0] = KlC[base]; blf[tt][1] = KlC[base + 4];
            }
#pragma unroll
            for (int tt = 0; tt < 4; ++tt) mma_bf16(s[tt], aH[ks], bhf[tt]);
#pragma unroll
            for (int tt = 0; tt < 4; ++tt) mma_bf16(s[tt], aH[ks], blf[tt]);
#pragma unroll
            for (int tt = 0; tt < 4; ++tt) mma_bf16(s[tt], aL[ks], bhf[tt]);
        }

        const bool isMem = (j0 < MEM_);
        if (!isMem) {
            const int il0 = W * 16 + g, il1 = il0 + 8;
#pragma unroll
            for (int tt = 0; tt < 4; ++tt) {
                int c0 = tt * 8 + 2 * qq;
                s[tt][0] += PdC[c0 * 132 + il0];
                s[tt][1] += PdC[(c0 + 1) * 132 + il0];
                s[tt][2] += PdC[c0 * 132 + il1];
                s[tt][3] += PdC[(c0 + 1) * 132 + il1];
            }
            const int jb = j0 - MEM_;
            if (jb + 31 > I0) {
                const int r0 = I0 + il0, r1 = r0 + 8;
#pragma unroll
                for (int tt = 0; tt < 4; ++tt) {
                    int c0 = jb + tt * 8 + 2 * qq;
                    if (c0     > r0) s[tt][0] = -1e30f;
                    if (c0 + 1 > r0) s[tt][1] = -1e30f;
                    if (c0     > r1) s[tt][2] = -1e30f;
                    if (c0 + 1 > r1) s[tt][3] = -1e30f;
                }
            }
        }

        // ---- online softmax ----
        float mt0 = fmaxf(fmaxf(s[0][0], s[0][1]), fmaxf(s[1][0], s[1][1]));
        mt0 = fmaxf(mt0, fmaxf(fmaxf(s[2][0], s[2][1]), fmaxf(s[3][0], s[3][1])));
        float mt1 = fmaxf(fmaxf(s[0][2], s[0][3]), fmaxf(s[1][2], s[1][3]));
        mt1 = fmaxf(mt1, fmaxf(fmaxf(s[2][2], s[2][3]), fmaxf(s[3][2], s[3][3])));
        mt0 = fmaxf(mt0, __shfl_xor_sync(0xffffffffu, mt0, 1));
        mt0 = fmaxf(mt0, __shfl_xor_sync(0xffffffffu, mt0, 2));
        mt1 = fmaxf(mt1, __shfl_xor_sync(0xffffffffu, mt1, 1));
        mt1 = fmaxf(mt1, __shfl_xor_sync(0xffffffffu, mt1, 2));
        float mn0 = fmaxf(m0, mt0), mn1 = fmaxf(m1, mt1);
        float f0 = __expf(m0 - mn0), f1 = __expf(m1 - mn1);
        l0 *= f0; l1 *= f1;
#pragma unroll
        for (int tt = 0; tt < 8; ++tt) {
            o[tt][0] *= f0; o[tt][1] *= f0;
            o[tt][2] *= f1; o[tt][3] *= f1;
        }
        m0 = mn0; m1 = mn1;

        unsigned pAh[4], pAl[4], pBh[4], pBl[4];
#pragma unroll
        for (int tt = 0; tt < 4; ++tt) {
            float p0 = __expf(s[tt][0] - m0);
            float p1 = __expf(s[tt][1] - m0);
            float p2 = __expf(s[tt][2] - m1);
            float p3 = __expf(s[tt][3] - m1);
            l0 += p0 + p1; l1 += p2 + p3;
            if (isMem) {
                float e0 = em_s[j0 + tt * 8 + 2 * qq];
                float e1 = em_s[j0 + tt * 8 + 2 * qq + 1];
                p0 *= e0; p1 *= e1; p2 *= e0; p3 *= e1;
            }
            bsplit2(p0, p1, pAh[tt], pAl[tt]);
            bsplit2(p2, p3, pBh[tt], pBl[tt]);
        }

        // ---- O += P V (pass-major) ----
#pragma unroll
        for (int ks = 0; ks < 2; ++ks) {
            unsigned ah[4] = { pAh[2 * ks], pBh[2 * ks], pAh[2 * ks + 1], pBh[2 * ks + 1] };
            unsigned al[4] = { pAl[2 * ks], pBl[2 * ks], pAl[2 * ks + 1], pBl[2 * ks + 1] };
            unsigned bhf[8][2], blf[8][2];
#pragma unroll
            for (int tt = 0; tt < 8; ++tt) {
                int base = (tt * 8 + g) * 36 + ks * 8 + qq;
                bhf[tt][0] = VhC[base]; bhf[tt][1] = VhC[base + 4];
                blf[tt][0] = VlC[base]; blf[tt][1] = VlC[base + 4];
            }
#pragma unroll
            for (int tt = 0; tt < 8; ++tt) mma_bf16(o[tt], ah, bhf[tt]);
#pragma unroll
            for (int tt = 0; tt < 8; ++tt) mma_bf16(o[tt], ah, blf[tt]);
#pragma unroll
            for (int tt = 0; tt < 8; ++tt) mma_bf16(o[tt], al, bhf[tt]);
        }
        __syncthreads();
    }

    l0 += __shfl_xor_sync(0xffffffffu, l0, 1);
    l0 += __shfl_xor_sync(0xffffffffu, l0, 2);
    l1 += __shfl_xor_sync(0xffffffffu, l1, 1);
    l1 += __shfl_xor_sync(0xffffffffu, l1, 2);
    float inv0 = 1.f / l0, inv1 = 1.f / l1;

    float* ob0 = O + ((size_t)(b * N_) + I0 + W * 16 + g) * DIM_ + h * DH_;
    float* ob1 = ob0 + 8 * DIM_;
#pragma unroll
    for (int tt = 0; tt < 8; ++tt) {
        int c0 = tt * 8 + 2 * qq;
        *(float2*)(ob0 + c0) = make_float2(o[tt][0] * inv0, o[tt][1] * inv0);
        *(float2*)(ob1 + c0) = make_float2(o[tt][2] * inv1, o[tt][3] * inv1);
    }
}

// ---------------- launcher ----------------
extern "C" void kernel_launch(void* const* d_in, const int* in_sizes, int n_in,
                              void* d_out, int out_size)
{
    const float* x       = (const float*)d_in[0];
    const float* pos_emb = (const float*)d_in[1];
    const float* mem     = (const float*)d_in[2];
    const float* expire  = (const float*)d_in[3];
    const float* Wq      = (const float*)d_in[4];
    const float* bq      = (const float*)d_in[5];
    const float* Wkv     = (const float*)d_in[6];
    const float* bkv     = (const float*)d_in[7];
    const float* Wo      = (const float*)d_in[8];
    const float* bo      = (const float*)d_in[9];
    const float* Wp      = (const float*)d_in[10];
    const float* bp      = (const float*)d_in[11];
    float* out = (float*)d_out;

    float *Q, *KV, *Pos, *Posp, *PDT, *O;
    unsigned *Kh, *Kl, *Vth, *Vtl;
    cudaGetSymbolAddress((void**)&Q,    g_Q);
    cudaGetSymbolAddress((void**)&KV,   g_KV);
    cudaGetSymbolAddress((void**)&Pos,  g_pos);
    cudaGetSymbolAddress((void**)&Posp, g_posp);
    cudaGetSymbolAddress((void**)&PDT,  g_PDT);
    cudaGetSymbolAddress((void**)&O,    g_O);
    cudaGetSymbolAddress((void**)&Kh,   g_Kh);
    cudaGetSymbolAddress((void**)&Kl,   g_Kl);
    cudaGetSymbolAddress((void**)&Vth,  g_Vth);
    cudaGetSymbolAddress((void**)&Vtl,  g_Vtl);

    cudaFuncSetAttribute(attn_kernel, cudaFuncAttributeMaxDynamicSharedMemorySize, SMEM_ATTN);

    // 1) Q = x @ Wq + bq
    gemm_bf16<<<dim3(DIM_ / 128, (B_ * N_) / 128, 1), 256>>>(
        x, B_ * N_, 0, x, 0, Wq, bq, Q, 0, DIM_, DIM_, nullptr, nullptr, 0);

    // 2) KV = concat(mem, x) @ Wkv + bkv  (also emits packed-bf16 K)
    gemm_bf16<<<dim3(2 * DIM_ / 128, CTX_ / 128, B_), 256>>>(
        mem, MEM_, (size_t)MEM_ * DIM_, x, (size_t)N_ * DIM_,
        Wkv, bkv, KV, (size_t)CTX_ * 2 * DIM_, 2 * DIM_, DIM_, Kh, Kl, DIM_);

    // 3) V^T split
    vt_kernel<<<dim3(CTX_ / 64, B_ * H_), 256>>>(KV, Vth, Vtl);

    // 4) pos' split-K
    pos_part<<<dim3(8, 32), 256>>>(pos_emb, Wp, Posp);
    pos_reduce<<<128, 256>>>(Posp, bp, Pos);

    // 5) PDT (shifted layout, tensor-core, coalesced writes)
    rd_kernel<<<dim3(16, 16, B_ * H_), 256>>>(Q, Pos, PDT);

    // 6) flash attention
    attn_kernel<<<dim3(N_ / 128, H_, B_), 256, SMEM_ATTN>>>(
        Q, Kh, Kl, Vth, Vtl, PDT, expire, O);

    // 7) out = O @ Wo + bo
    gemm_bf16<<<dim3(DIM_ / 128, (B_ * N_) / 128, 1), 256>>>(
        O, B_ * N_, 0, O, 0, Wo, bo, out, 0, DIM_, DIM_, nullptr, nullptr, 0);
}

// round 14
// speedup vs baseline: 1.2640x; 1.2640x over previous
#include <cuda_runtime.h>
#include <cuda_bf16.h>
#include <cstdint>
#include <cstddef>

#define B_    2
#define N_    2048
#define DIM_  1024
#define H_    16
#define DH_   64
#define MEM_  1024
#define CTX_  3072
#define SCALE_ 0.125f

// ---------------- scratch (static device globals; no allocation) ----------------
__device__ float    g_Q  [B_ * N_ * DIM_];         // 16 MB
__device__ float    g_KV [B_ * CTX_ * 2 * DIM_];   // 48 MB
__device__ float    g_pos[N_ * DH_];               // 512 KB
__device__ float    g_posp[8 * N_ * DH_];          // 4 MB  split-K partials
__device__ float    g_RD [134217728];              // 512 MB RD[b,h][i][p]
__device__ float    g_O  [B_ * N_ * DIM_];         // 16 MB
__device__ unsigned g_Kh [B_ * CTX_ * 512];        // K hi (bf16x2, feature pairs)
__device__ unsigned g_Kl [B_ * CTX_ * 512];        // K lo
__device__ unsigned g_Vth[B_ * H_ * DH_ * (CTX_/2)]; // V^T hi (key pairs)
__device__ unsigned g_Vtl[B_ * H_ * DH_ * (CTX_/2)]; // V^T lo

// =====================================================================
// bf16x3 helpers
// =====================================================================
__device__ __forceinline__ void bsplit2(float x, float y, unsigned& h, unsigned& l)
{
    asm("cvt.rn.bf16x2.f32 %0, %1, %2;" : "=r"(h) : "f"(y), "f"(x));
    float xr = x - __uint_as_float(h << 16);
    float yr = y - __uint_as_float(h & 0xFFFF0000u);
    asm("cvt.rn.bf16x2.f32 %0, %1, %2;" : "=r"(l) : "f"(yr), "f"(xr));
}

__device__ __forceinline__ void mma_bf16(float* c, const unsigned* a, const unsigned* b)
{
    asm volatile(
        "mma.sync.aligned.m16n8k16.row.col.f32.bf16.bf16.f32 "
        "{%0,%1,%2,%3}, {%4,%5,%6,%7}, {%8,%9}, {%0,%1,%2,%3};\n"
        : "+f"(c[0]), "+f"(c[1]), "+f"(c[2]), "+f"(c[3])
        : "r"(a[0]), "r"(a[1]), "r"(a[2]), "r"(a[3]), "r"(b[0]), "r"(b[1]));
}

__device__ __forceinline__ void cp_async16(void* s, const void* g)
{
    unsigned a = (unsigned)__cvta_generic_to_shared(s);
    asm volatile("cp.async.cg.shared.global [%0], [%1], 16;" :: "r"(a), "l"(g));
}

// =====================================================================
// Split-bf16 tensor-core GEMM:  C = A @ B + bias  (bf16x3, m16n8k16)
// =====================================================================
__global__ __launch_bounds__(256) void gemm_bf16(
    const float* __restrict__ Alo, int MLo, size_t sAlo,
    const float* __restrict__ Ahi, size_t sAhi,
    const float* __restrict__ Bm, const float* __restrict__ bias,
    float* __restrict__ C, size_t sC,
    int N, int K,
    unsigned* __restrict__ Kh, unsigned* __restrict__ Kl, int kcols)
{
    __shared__ __align__(16) unsigned AsH[128][12];
    __shared__ __align__(16) unsigned AsL[128][12];
    __shared__ __align__(16) unsigned BsH[8][136];
    __shared__ __align__(16) unsigned BsL[8][136];

    const int batch   = blockIdx.z;
    const int rowBase = blockIdx.y * 128;
    const int colBase = blockIdx.x * 128;
    const int tid  = threadIdx.x;
    const int wid  = tid >> 5, lane = tid & 31;
    const int wm   = wid & 3,  wn   = wid >> 2;
    const int g    = lane >> 2, qq  = lane & 3;

    const int ar = tid >> 2;
    const int ac = (tid & 3) * 4;
    const float* aptr[2];
#pragma unroll
    for (int i = 0; i < 2; ++i) {
        int r = rowBase + ar + 64 * i;
        aptr[i] = ((r < MLo) ? (Alo + (size_t)batch * sAlo + (size_t)r * K)
                             : (Ahi + (size_t)batch * sAhi + (size_t)(r - MLo) * K)) + ac;
    }
    const int kp = tid >> 5;
    const int n0 = (tid & 31) * 4;
    const float* bptr0 = Bm + (size_t)(2 * kp) * N + colBase + n0;
    const float* bptr1 = bptr0 + N;

    float4 ga[2], gb0, gb1;
#pragma unroll
    for (int i = 0; i < 2; ++i) ga[i] = *(const float4*)(aptr[i]);
    gb0 = *(const float4*)(bptr0);
    gb1 = *(const float4*)(bptr1);

    float acc[2][8][4];
#pragma unroll
    for (int a = 0; a < 2; ++a)
#pragma unroll
        for (int b = 0; b < 8; ++b)
#pragma unroll
            for (int c = 0; c < 4; ++c) acc[a][b][c] = 0.f;

    for (int k0 = 0; k0 < K; k0 += 16) {
#pragma unroll
        for (int i = 0; i < 2; ++i) {
            unsigned h0, l0, h1, l1;
            bsplit2(ga[i].x, ga[i].y, h0, l0);
            bsplit2(ga[i].z, ga[i].w, h1, l1);
            int r = ar + 64 * i, cpr = ac >> 1;
            AsH[r][cpr] = h0; AsH[r][cpr + 1] = h1;
            AsL[r][cpr] = l0; AsL[r][cpr + 1] = l1;
        }
        {
            uint4 bh, bl;
            bsplit2(gb0.x, gb1.x, bh.x, bl.x);
            bsplit2(gb0.y, gb1.y, bh.y, bl.y);
            bsplit2(gb0.z, gb1.z, bh.z, bl.z);
            bsplit2(gb0.w, gb1.w, bh.w, bl.w);
            *(uint4*)&BsH[kp][n0] = bh;
            *(uint4*)&BsL[kp][n0] = bl;
        }
        __syncthreads();

        if (k0 + 16 < K) {
#pragma unroll
            for (int i = 0; i < 2; ++i) ga[i] = *(const float4*)(aptr[i] + k0 + 16);
            gb0 = *(const float4*)(bptr0 + (size_t)(k0 + 16) * N);
            gb1 = *(const float4*)(bptr1 + (size_t)(k0 + 16) * N);
        }

        unsigned bH[8][2], bL[8][2];
#pragma unroll
        for (int tn = 0; tn < 8; ++tn) {
            int col = wn * 64 + tn * 8 + g;
            bH[tn][0] = BsH[qq][col]; bH[tn][1] = BsH[qq + 4][col];
            bL[tn][0] = BsL[qq][col]; bL[tn][1] = BsL[qq + 4][col];
        }
#pragma unroll
        for (int tm = 0; tm < 2; ++tm) {
            int r0 = wm * 32 + tm * 16 + g;
            unsigned aHf[4], aLf[4];
            aHf[0] = AsH[r0][qq];     aHf[1] = AsH[r0 + 8][qq];
            aHf[2] = AsH[r0][qq + 4]; aHf[3] = AsH[r0 + 8][qq + 4];
            aLf[0] = AsL[r0][qq];     aLf[1] = AsL[r0 + 8][qq];
            aLf[2] = AsL[r0][qq + 4]; aLf[3] = AsL[r0 + 8][qq + 4];
#pragma unroll
            for (int tn = 0; tn < 8; ++tn) mma_bf16(acc[tm][tn], aHf, bH[tn]);
#pragma unroll
            for (int tn = 0; tn < 8; ++tn) mma_bf16(acc[tm][tn], aHf, bL[tn]);
#pragma unroll
            for (int tn = 0; tn < 8; ++tn) mma_bf16(acc[tm][tn], aLf, bH[tn]);
        }
        __syncthreads();
    }

    float* Cb = C + (size_t)batch * sC;
#pragma unroll
    for (int tm = 0; tm < 2; ++tm) {
#pragma unroll
        for (int tn = 0; tn < 8; ++tn) {
            int row = rowBase + wm * 32 + tm * 16 + g;
            int col = colBase + wn * 64 + tn * 8 + 2 * qq;
            float b0 = bias[col], b1 = bias[col + 1];
            float2 v0 = make_float2(acc[tm][tn][0] + b0, acc[tm][tn][1] + b1);
            float2 v1 = make_float2(acc[tm][tn][2] + b0, acc[tm][tn][3] + b1);
            *(float2*)(Cb + (size_t)row * N + col) = v0;
            *(float2*)(Cb + (size_t)(row + 8) * N + col) = v1;
            if (Kh != nullptr && col < kcols) {
                unsigned hh, ll;
                size_t kr = ((size_t)batch * CTX_ + row) * (kcols >> 1) + (col >> 1);
                bsplit2(v0.x, v0.y, hh, ll);
                Kh[kr] = hh; Kl[kr] = ll;
                bsplit2(v1.x, v1.y, hh, ll);
                size_t kr2 = kr + (size_t)8 * (kcols >> 1);
                Kh[kr2] = hh; Kl[kr2] = ll;
            }
        }
    }
}

// =====================================================================
// pos' split-K
// =====================================================================
__global__ __launch_bounds__(256) void pos_part(
    const float* __restrict__ A, const float* __restrict__ Bm, float* __restrict__ Cp)
{
    __shared__ float As[16][65];
    __shared__ float Bs[16][64];

    const int kOff    = blockIdx.x * 128;
    const int rowBase = blockIdx.y * 64;
    const int tid = threadIdx.x;
    const int tx = tid & 15, ty = tid >> 4;

    const int arow = tid >> 2;
    const int ac   = (tid & 3) * 4;
    const int brow = tid >> 4;
    const int bc   = (tid & 15) * 4;

    const float* Aptr = A + (size_t)(rowBase + arow) * DIM_ + kOff;
    float acc[4][4] = {};

    for (int k0 = 0; k0 < 128; k0 += 16) {
        float4 av = *(const float4*)(Aptr + k0 + ac);
        float4 bv = *(const float4*)(Bm + (size_t)(kOff + k0 + brow) * DH_ + bc);
        __syncthreads();
        As[ac + 0][arow] = av.x; As[ac + 1][arow] = av.y;
        As[ac + 2][arow] = av.z; As[ac + 3][arow] = av.w;
        *(float4*)&Bs[brow][bc] = bv;
        __syncthreads();
#pragma unroll
        for (int kk = 0; kk < 16; ++kk) {
            float a0 = As[kk][ty * 4 + 0], a1 = As[kk][ty * 4 + 1];
            float a2 = As[kk][ty * 4 + 2], a3 = As[kk][ty * 4 + 3];
            float4 b4 = *(const float4*)&Bs[kk][tx * 4];
            acc[0][0] += a0 * b4.x; acc[0][1] += a0 * b4.y; acc[0][2] += a0 * b4.z; acc[0][3] += a0 * b4.w;
            acc[1][0] += a1 * b4.x; acc[1][1] += a1 * b4.y; acc[1][2] += a1 * b4.z; acc[1][3] += a1 * b4.w;
            acc[2][0] += a2 * b4.x; acc[2][1] += a2 * b4.y; acc[2][2] += a2 * b4.z; acc[2][3] += a2 * b4.w;
            acc[3][0] += a3 * b4.x; acc[3][1] += a3 * b4.y; acc[3][2] += a3 * b4.z; acc[3][3] += a3 * b4.w;
        }
    }

    float* Cb = Cp + (size_t)blockIdx.x * (N_ * DH_);
#pragma unroll
    for (int a = 0; a < 4; ++a) {
        int row = rowBase + ty * 4 + a;
        *(float4*)(Cb + (size_t)row * DH_ + tx * 4) =
            make_float4(acc[a][0], acc[a][1], acc[a][2], acc[a][3]);
    }
}

__global__ __launch_bounds__(256) void pos_reduce(
    const float* __restrict__ Cp, const float* __restrict__ bias, float* __restrict__ C)
{
    int i4 = blockIdx.x * 256 + threadIdx.x;
    float4 s = ((const float4*)Cp)[i4];
#pragma unroll
    for (int k = 1; k < 8; ++k) {
        float4 t = ((const float4*)(Cp + (size_t)k * (N_ * DH_)))[i4];
        s.x += t.x; s.y += t.y; s.z += t.z; s.w += t.w;
    }
    int col = (i4 & 15) * 4;
    float4 bv = *(const float4*)(bias + col);
    s.x += bv.x; s.y += bv.y; s.z += bv.z; s.w += bv.w;
    ((float4*)C)[i4] = s;
}

// =====================================================================
// vt_kernel: V^T split
// =====================================================================
__global__ __launch_bounds__(256) void vt_kernel(
    const float* __restrict__ KV, unsigned* __restrict__ Vth, unsigned* __restrict__ Vtl)
{
    const int bh = blockIdx.y;
    const int b = bh >> 4, h = bh & 15;
    const int J0 = blockIdx.x * 64;
    __shared__ float Vs[64][65];
    const int tid = threadIdx.x;

#pragma unroll
    for (int u = 0; u < 4; ++u) {
        int idx = u * 256 + tid;
        int row = idx >> 4, c4 = (idx & 15) * 4;
        float4 v = *(const float4*)(KV + ((size_t)b * CTX_ + J0 + row) * (2 * DIM_) + DIM_ + h * DH_ + c4);
        Vs[row][c4] = v.x; Vs[row][c4 + 1] = v.y; Vs[row][c4 + 2] = v.z; Vs[row][c4 + 3] = v.w;
    }
    __syncthreads();

#pragma unroll
    for (int u = 0; u < 8; ++u) {
        int idx = u * 256 + tid;
        int d = idx >> 5, jp = idx & 31;
        unsigned hh, ll;
        bsplit2(Vs[2 * jp][d], Vs[2 * jp + 1][d], hh, ll);
        size_t o = ((size_t)bh * DH_ + d) * (CTX_ / 2) + (J0 >> 1) + jp;
        Vth[o] = hh; Vtl[o] = ll;
    }
}

// =====================================================================
// rd_kernel: RD[b,h][i][p] = SCALE * q_i . pos'_p  (bf16x3, band-culled)
// =====================================================================
__global__ __launch_bounds__(256) void rd_kernel(
    const float* __restrict__ Q, const float* __restrict__ Pos, float* __restrict__ RD)
{
    const int I0 = blockIdx.y * 128;
    const int P0 = blockIdx.x * 128;
    if (I0 + P0 + 254 < 2047) return;

    const int bh = blockIdx.z;
    const int b  = bh >> 4, h = bh & 15;

    __shared__ unsigned PsH[128][36];
    __shared__ unsigned PsL[128][36];

    const int tid  = threadIdx.x;
    const int wid  = tid >> 5, lane = tid & 31;
    const int wm   = wid & 3,  wn   = wid >> 2;
    const int g    = lane >> 2, qq  = lane & 3;

#pragma unroll
    for (int u = 0; u < 8; ++u) {
        int idx = tid + u * 256;
        int prow = idx >> 4, c4 = (idx & 15) * 4;
        float4 v = *(const float4*)(Pos + (size_t)(P0 + prow) * DH_ + c4);
        unsigned h0, l0, h1, l1;
        bsplit2(v.x, v.y, h0, l0);
        bsplit2(v.z, v.w, h1, l1);
        int pc = (idx & 15) * 2;
        PsH[prow][pc] = h0; PsH[prow][pc + 1] = h1;
        PsL[prow][pc] = l0; PsL[prow][pc + 1] = l1;
    }

    unsigned aH[2][4][4], aL[2][4][4];
#pragma unroll
    for (int tm = 0; tm < 2; ++tm) {
        const float* q0 = Q + ((size_t)(b * N_) + I0 + wm * 32 + tm * 16 + g) * DIM_ + h * DH_;
        const float* q8 = q0 + 8 * DIM_;
#pragma unroll
        for (int ks = 0; ks < 4; ++ks) {
            float2 xa = *(const float2*)(q0 + ks * 16 + 2 * qq);
            float2 xb = *(const float2*)(q0 + ks * 16 + 2 * qq + 8);
            float2 ya = *(const float2*)(q8 + ks * 16 + 2 * qq);
            float2 yb = *(const float2*)(q8 + ks * 16 + 2 * qq + 8);
            bsplit2(xa.x, xa.y, aH[tm][ks][0], aL[tm][ks][0]);
            bsplit2(ya.x, ya.y, aH[tm][ks][1], aL[tm][ks][1]);
            bsplit2(xb.x, xb.y, aH[tm][ks][2], aL[tm][ks][2]);
            bsplit2(yb.x, yb.y, aH[tm][ks][3], aL[tm][ks][3]);
        }
    }
    __syncthreads();

    float acc[2][8][4];
#pragma unroll
    for (int a = 0; a < 2; ++a)
#pragma unroll
        for (int t = 0; t < 8; ++t)
#pragma unroll
            for (int c = 0; c < 4; ++c) acc[a][t][c] = 0.f;

#pragma unroll
    for (int ks = 0; ks < 4; ++ks) {
#pragma unroll
        for (int tn = 0; tn < 8; ++tn) {
            int col = wn * 64 + tn * 8 + g;
            unsigned bh2[2], bl2[2];
            bh2[0] = PsH[col][8 * ks + qq];     bh2[1] = PsH[col][8 * ks + qq + 4];
            bl2[0] = PsL[col][8 * ks + qq];     bl2[1] = PsL[col][8 * ks + qq + 4];
            mma_bf16(acc[0][tn], aH[0][ks], bh2);
            mma_bf16(acc[1][tn], aH[1][ks], bh2);
            mma_bf16(acc[0][tn], aH[0][ks], bl2);
            mma_bf16(acc[1][tn], aH[1][ks], bl2);
            mma_bf16(acc[0][tn], aL[0][ks], bh2);
            mma_bf16(acc[1][tn], aL[1][ks], bh2);
        }
    }

    float* base = RD + ((size_t)bh << 22);
#pragma unroll
    for (int tm = 0; tm < 2; ++tm) {
#pragma unroll
        for (int tn = 0; tn < 8; ++tn) {
            int row = I0 + wm * 32 + tm * 16 + g;
            int col = P0 + wn * 64 + tn * 8 + 2 * qq;
            float* dst = base + (size_t)row * N_ + col;
            *(float2*)dst = make_float2(acc[tm][tn][0] * SCALE_, acc[tm][tn][1] * SCALE_);
            *(float2*)(dst + 8 * N_) = make_float2(acc[tm][tn][2] * SCALE_, acc[tm][tn][3] * SCALE_);
        }
    }
}

// =====================================================================
// Tensor-core flash attention (bf16x3; K/V pre-split; RD gathers hoisted
// above the mma block so L2 latency overlaps tensor work)
// =====================================================================
#define KW   36
#define SM_K (32 * KW)
#define SM_V (64 * KW)
#define OFF_KL 2304
#define OFF_VH 4608
#define OFF_VL 9216
#define OFF_EM 13824
#define SMEM_ATTN ((OFF_EM + 1024) * 4)   // 59392 B

__device__ __forceinline__ void load_kv_stage(
    unsigned* smu, int sb, int jt, int tid, int b, int bh64,
    const unsigned* __restrict__ Khg, const unsigned* __restrict__ Klg,
    const unsigned* __restrict__ Vthg, const unsigned* __restrict__ Vtlg, int h)
{
    unsigned* KhD = smu + sb * SM_K;
    unsigned* KlD = smu + OFF_KL + sb * SM_K;
    unsigned* VhD = smu + OFF_VH + sb * SM_V;
    unsigned* VlD = smu + OFF_VL + sb * SM_V;
#pragma unroll
    for (int u = 0; u < 2; ++u) {
        int e = u * 128 + tid;
        int row = e >> 3, part = e & 7;
        size_t srk = ((size_t)b * CTX_ + jt + row) * 512 + h * 32 + part * 4;
        cp_async16(KhD + row * KW + part * 4, Khg + srk);
        cp_async16(KlD + row * KW + part * 4, Klg + srk);
    }
#pragma unroll
    for (int u = 0; u < 2; ++u) {
        int e = u * 128 + tid;
        int row = e >> 2, part = e & 3;
        size_t srv = ((size_t)bh64 + row) * (CTX_ / 2) + (jt >> 1) + part * 4;
        cp_async16(VhD + row * KW + part * 4, Vthg + srv);
        cp_async16(VlD + row * KW + part * 4, Vtlg + srv);
    }
}

__global__ __launch_bounds__(128, 3) void attn_kernel(
    const float* __restrict__ Q,
    const unsigned* __restrict__ Khg, const unsigned* __restrict__ Klg,
    const unsigned* __restrict__ Vthg, const unsigned* __restrict__ Vtlg,
    const float* __restrict__ RD, const float* __restrict__ expire,
    float* __restrict__ O)
{
    extern __shared__ unsigned smu[];
    float* em_s = (float*)(smu + OFF_EM);

    const int b = blockIdx.z, h = blockIdx.y;
    const int tid = threadIdx.x;
    const int I0 = blockIdx.x * 64;
    const int W = tid >> 5, lane = tid & 31;
    const int g = lane >> 2, qq = lane & 3;
    const int bh64 = (b * H_ + h) * DH_;

    {
        const float* emp = expire + b * MEM_;
        *(float4*)&em_s[tid * 8]     = *(const float4*)(emp + tid * 8);
        *(float4*)&em_s[tid * 8 + 4] = *(const float4*)(emp + tid * 8 + 4);
    }

    unsigned aH[4][4], aL[4][4];
    {
        const float* q0 = Q + ((size_t)(b * N_) + I0 + W * 16 + g) * DIM_ + h * DH_;
        const float* q8 = q0 + 8 * DIM_;
#pragma unroll
        for (int ks = 0; ks < 4; ++ks) {
            float2 xa = *(const float2*)(q0 + ks * 16 + 2 * qq);
            float2 xb = *(const float2*)(q0 + ks * 16 + 2 * qq + 8);
            float2 ya = *(const float2*)(q8 + ks * 16 + 2 * qq);
            float2 yb = *(const float2*)(q8 + ks * 16 + 2 * qq + 8);
            bsplit2(xa.x * SCALE_, xa.y * SCALE_, aH[ks][0], aL[ks][0]);
            bsplit2(ya.x * SCALE_, ya.y * SCALE_, aH[ks][1], aL[ks][1]);
            bsplit2(xb.x * SCALE_, xb.y * SCALE_, aH[ks][2], aL[ks][2]);
            bsplit2(yb.x * SCALE_, yb.y * SCALE_, aH[ks][3], aL[ks][3]);
        }
    }

    float o[8][4];
#pragma unroll
    for (int t = 0; t < 8; ++t)
#pragma unroll
        for (int c = 0; c < 4; ++c) o[t][c] = 0.f;
    float m0 = -1e30f, m1 = -1e30f, l0 = 0.f, l1 = 0.f;

    const float* rdb = RD + (((size_t)(b * H_ + h)) << 22);
    const int ntiles = (MEM_ + I0 + 64) / 32;

    // precomputed RD row pointers / offsets for this thread
    const int i0g = I0 + W * 16 + g;
    const float* rd0 = rdb + (size_t)i0g * N_;
    const float* rd1 = rd0 + 8 * N_;

    load_kv_stage(smu, 0, 0, tid, b, bh64, Khg, Klg, Vthg, Vtlg, h);
    asm volatile("cp.async.commit_group;");

    for (int t = 0; t < ntiles; ++t) {
        const int st = t & 1;
        const int j0 = t * 32;
        if (t + 1 < ntiles)
            load_kv_stage(smu, st ^ 1, j0 + 32, tid, b, bh64, Khg, Klg, Vthg, Vtlg, h);
        asm volatile("cp.async.commit_group;");
        asm volatile("cp.async.wait_group 1;");
        __syncthreads();

        const unsigned* KhC = smu + st * SM_K;
        const unsigned* KlC = smu + OFF_KL + st * SM_K;
        const unsigned* VhC = smu + OFF_VH + st * SM_V;
        const unsigned* VlC = smu + OFF_VL + st * SM_V;

        const bool isMem = (j0 < MEM_);

        // ---- HOISTED RD gathers: issue loads BEFORE the mma burst ----
        float pd[4][4];
        if (!isMem) {
            const int jb = j0 - MEM_;
            const int D0 = jb + 2047 - i0g;
            const int D1 = D0 - 8;
#pragma unroll
            for (int tt = 0; tt < 4; ++tt) {
                int c0 = tt * 8 + 2 * qq;
                int p00 = D0 + c0;     p00 = p00 > 2047 ? 2047 : p00;
                int p01 = D0 + c0 + 1; p01 = p01 > 2047 ? 2047 : p01;
                int p10 = D1 + c0;     p10 = p10 > 2047 ? 2047 : p10;
                int p11 = D1 + c0 + 1; p11 = p11 > 2047 ? 2047 : p11;
                pd[tt][0] = rd0[p00];
                pd[tt][1] = rd0[p01];
                pd[tt][2] = rd1[p10];
                pd[tt][3] = rd1[p11];
            }
        }

        // ---- S = Q K^T (pass-major) ----
        float s[4][4];
#pragma unroll
        for (int tt = 0; tt < 4; ++tt)
#pragma unroll
            for (int c = 0; c < 4; ++c) s[tt][c] = 0.f;

#pragma unroll
        for (int ks = 0; ks < 4; ++ks) {
            unsigned bhf[4][2], blf[4][2];
#pragma unroll
            for (int tt = 0; tt < 4; ++tt) {
                int base = (tt * 8 + g) * KW + ks * 8 + qq;
                bhf[tt][0] = KhC[base]; bhf[tt][1] = KhC[base + 4];
                blf[tt][0] = KlC[base]; blf[tt][1] = KlC[base + 4];
            }
#pragma unroll
            for (int tt = 0; tt < 4; ++tt) mma_bf16(s[tt], aH[ks], bhf[tt]);
#pragma unroll
            for (int tt = 0; tt < 4; ++tt) mma_bf16(s[tt], aH[ks], blf[tt]);
#pragma unroll
            for (int tt = 0; tt < 4; ++tt) mma_bf16(s[tt], aL[ks], bhf[tt]);
        }

        if (!isMem) {
            const int jb = j0 - MEM_;
#pragma unroll
            for (int tt = 0; tt < 4; ++tt) {
                s[tt][0] += pd[tt][0];
                s[tt][1] += pd[tt][1];
                s[tt][2] += pd[tt][2];
                s[tt][3] += pd[tt][3];
            }
            if (jb + 31 > I0) {
                const int r0 = i0g, r1 = i0g + 8;
#pragma unroll
                for (int tt = 0; tt < 4; ++tt) {
                    int c0 = jb + tt * 8 + 2 * qq;
                    if (c0     > r0) s[tt][0] = -1e30f;
                    if (c0 + 1 > r0) s[tt][1] = -1e30f;
                    if (c0     > r1) s[tt][2] = -1e30f;
                    if (c0 + 1 > r1) s[tt][3] = -1e30f;
                }
            }
        }

        // ---- online softmax ----
        float mt0 = fmaxf(fmaxf(s[0][0], s[0][1]), fmaxf(s[1][0], s[1][1]));
        mt0 = fmaxf(mt0, fmaxf(fmaxf(s[2][0], s[2][1]), fmaxf(s[3][0], s[3][1])));
        float mt1 = fmaxf(fmaxf(s[0][2], s[0][3]), fmaxf(s[1][2], s[1][3]));
        mt1 = fmaxf(mt1, fmaxf(fmaxf(s[2][2], s[2][3]), fmaxf(s[3][2], s[3][3])));
        mt0 = fmaxf(mt0, __shfl_xor_sync(0xffffffffu, mt0, 1));
        mt0 = fmaxf(mt0, __shfl_xor_sync(0xffffffffu, mt0, 2));
        mt1 = fmaxf(mt1, __shfl_xor_sync(0xffffffffu, mt1, 1));
        mt1 = fmaxf(mt1, __shfl_xor_sync(0xffffffffu, mt1, 2));
        float mn0 = fmaxf(m0, mt0), mn1 = fmaxf(m1, mt1);
        float f0 = __expf(m0 - mn0), f1 = __expf(m1 - mn1);
        l0 *= f0; l1 *= f1;
#pragma unroll
        for (int tt = 0; tt < 8; ++tt) {
            o[tt][0] *= f0; o[tt][1] *= f0;
            o[tt][2] *= f1; o[tt][3] *= f1;
        }
        m0 = mn0; m1 = mn1;

        unsigned pAh[4], pAl[4], pBh[4], pBl[4];
#pragma unroll
        for (int tt = 0; tt < 4; ++tt) {
            float p0 = __expf(s[tt][0] - m0);
            float p1 = __expf(s[tt][1] - m0);
            float p2 = __expf(s[tt][2] - m1);
            float p3 = __expf(s[tt][3] - m1);
            l0 += p0 + p1; l1 += p2 + p3;
            if (isMem) {
                float e0 = em_s[j0 + tt * 8 + 2 * qq];
                float e1 = em_s[j0 + tt * 8 + 2 * qq + 1];
                p0 *= e0; p1 *= e1; p2 *= e0; p3 *= e1;
            }
            bsplit2(p0, p1, pAh[tt], pAl[tt]);
            bsplit2(p2, p3, pBh[tt], pBl[tt]);
        }

        // ---- O += P V (pass-major) ----
#pragma unroll
        for (int ks = 0; ks < 2; ++ks) {
            unsigned ah[4] = { pAh[2 * ks], pBh[2 * ks], pAh[2 * ks + 1], pBh[2 * ks + 1] };
            unsigned al[4] = { pAl[2 * ks], pBl[2 * ks], pAl[2 * ks + 1], pBl[2 * ks + 1] };
            unsigned bhf[8][2], blf[8][2];
#pragma unroll
            for (int tt = 0; tt < 8; ++tt) {
                int base = (tt * 8 + g) * KW + ks * 8 + qq;
                bhf[tt][0] = VhC[base]; bhf[tt][1] = VhC[base + 4];
                blf[tt][0] = VlC[base]; blf[tt][1] = VlC[base + 4];
            }
#pragma unroll
            for (int tt = 0; tt < 8; ++tt) mma_bf16(o[tt], ah, bhf[tt]);
#pragma unroll
            for (int tt = 0; tt < 8; ++tt) mma_bf16(o[tt], ah, blf[tt]);
#pragma unroll
            for (int tt = 0; tt < 8; ++tt) mma_bf16(o[tt], al, bhf[tt]);
        }
        __syncthreads();
    }

    l0 += __shfl_xor_sync(0xffffffffu, l0, 1);
    l0 += __shfl_xor_sync(0xffffffffu, l0, 2);
    l1 += __shfl_xor_sync(0xffffffffu, l1, 1);
    l1 += __shfl_xor_sync(0xffffffffu, l1, 2);
    float inv0 = 1.f / l0, inv1 = 1.f / l1;

    float* ob0 = O + ((size_t)(b * N_) + I0 + W * 16 + g) * DIM_ + h * DH_;
    float* ob1 = ob0 + 8 * DIM_;
#pragma unroll
    for (int tt = 0; tt < 8; ++tt) {
        int c0 = tt * 8 + 2 * qq;
        *(float2*)(ob0 + c0) = make_float2(o[tt][0] * inv0, o[tt][1] * inv0);
        *(float2*)(ob1 + c0) = make_float2(o[tt][2] * inv1, o[tt][3] * inv1);
    }
}

// ---------------- launcher ----------------
extern "C" void kernel_launch(void* const* d_in, const int* in_sizes, int n_in,
                              void* d_out, int out_size)
{
    const float* x       = (const float*)d_in[0];
    const float* pos_emb = (const float*)d_in[1];
    const float* mem     = (const float*)d_in[2];
    const float* expire  = (const float*)d_in[3];
    const float* Wq      = (const float*)d_in[4];
    const float* bq      = (const float*)d_in[5];
    const float* Wkv     = (const float*)d_in[6];
    const float* bkv     = (const float*)d_in[7];
    const float* Wo      = (const float*)d_in[8];
    const float* bo      = (const float*)d_in[9];
    const float* Wp      = (const float*)d_in[10];
    const float* bp      = (const float*)d_in[11];
    float* out = (float*)d_out;

    float *Q, *KV, *Pos, *Posp, *RD, *O;
    unsigned *Kh, *Kl, *Vth, *Vtl;
    cudaGetSymbolAddress((void**)&Q,    g_Q);
    cudaGetSymbolAddress((void**)&KV,   g_KV);
    cudaGetSymbolAddress((void**)&Pos,  g_pos);
    cudaGetSymbolAddress((void**)&Posp, g_posp);
    cudaGetSymbolAddress((void**)&RD,   g_RD);
    cudaGetSymbolAddress((void**)&O,    g_O);
    cudaGetSymbolAddress((void**)&Kh,   g_Kh);
    cudaGetSymbolAddress((void**)&Kl,   g_Kl);
    cudaGetSymbolAddress((void**)&Vth,  g_Vth);
    cudaGetSymbolAddress((void**)&Vtl,  g_Vtl);

    cudaFuncSetAttribute(attn_kernel, cudaFuncAttributeMaxDynamicSharedMemorySize, SMEM_ATTN);

    // 1) Q = x @ Wq + bq
    gemm_bf16<<<dim3(DIM_ / 128, (B_ * N_) / 128, 1), 256>>>(
        x, B_ * N_, 0, x, 0, Wq, bq, Q, 0, DIM_, DIM_, nullptr, nullptr, 0);

    // 2) KV = concat(mem, x) @ Wkv + bkv  (also emits packed-bf16 K)
    gemm_bf16<<<dim3(2 * DIM_ / 128, CTX_ / 128, B_), 256>>>(
        mem, MEM_, (size_t)MEM_ * DIM_, x, (size_t)N_ * DIM_,
        Wkv, bkv, KV, (size_t)CTX_ * 2 * DIM_, 2 * DIM_, DIM_, Kh, Kl, DIM_);

    // 3) V^T split
    vt_kernel<<<dim3(CTX_ / 64, B_ * H_), 256>>>(KV, Vth, Vtl);

    // 4) pos' split-K
    pos_part<<<dim3(8, 32), 256>>>(pos_emb, Wp, Posp);
    pos_reduce<<<128, 256>>>(Posp, bp, Pos);

    // 5) RD = SCALE * Q_head @ pos'^T  (band-culled)
    rd_kernel<<<dim3(16, 16, B_ * H_), 256>>>(Q, Pos, RD);

    // 6) tensor-core flash attention -> O
    attn_kernel<<<dim3(N_ / 64, H_, B_), 128, SMEM_ATTN>>>(
        Q, Kh, Kl, Vth, Vtl, RD, expire, O);

    // 7) out = O @ Wo + bo
    gemm_bf16<<<dim3(DIM_ / 128, (B_ * N_) / 128, 1), 256>>>(
        O, B_ * N_, 0, O, 0, Wo, bo, out, 0, DIM_, DIM_, nullptr, nullptr, 0);
}